// round 11
// baseline (speedup 1.0000x reference)
#include <cuda_runtime.h>
#include <math.h>

#define BB 16
#define NN 2048
#define MM 32
#define PP 48
#define TT 5
#define CC (PP*TT)   // 240

#define APB 8            // atoms per chunk
#define TH1 (APB*PP)     // 384 threads = 12 warps; phase A uses warps 0..7
#define GRID 296         // 2 blocks/SM on 148+ SMs -> all co-resident
#define NCHUNK ((BB*NN)/APB)   // 4096 rsf work items

// Per-atom BN partials: g_part[atom] = {sum, sumsq} over 240 channels.
__device__ float2 g_part[BB * NN];
// Monotonic grid barrier counter (never reset; target rounds up to next
// multiple of GRID, so graph replays are safe).
__device__ unsigned g_bar;

__device__ __forceinline__ float ex2_fast(float x) {
    float r; asm("ex2.approx.f32 %0, %1;" : "=f"(r) : "f"(x)); return r;
}
__device__ __forceinline__ float sqrt_fast(float x) {
    float r; asm("sqrt.approx.f32 %0, %1;" : "=f"(r) : "f"(x)); return r;
}

// ---------------------------------------------------------------------------
// Fused persistent kernel: rsf over all atoms, grid barrier, then BatchNorm.
// ---------------------------------------------------------------------------
__global__ __launch_bounds__(TH1, 2)
void fused_kernel(const float* __restrict__ X,
                  const float* __restrict__ rc,
                  const float* __restrict__ rs,
                  const float* __restrict__ re,
                  const int*   __restrict__ Nbrs,
                  const int*   __restrict__ NbrsZ,
                  float*       __restrict__ out)
{
    __shared__ float2 sRT[APB][MM];
    __shared__ int    sCnt[APB];
    __shared__ float2 sPart[TH1];
    __shared__ float  sMean, sInv;

    const int tid  = threadIdx.x;
    const int warp = tid >> 5;
    const int lane = tid & 31;

    // Per-thread radial params (loop-invariant across chunks).
    const int g = tid / PP;        // atom within chunk
    const int j = tid % PP;        // radial index p
    const float myrc  = rc[j];
    const float myrs  = rs[j];
    const float nre2  = -re[j] * 1.44269504088896f;  // fold log2(e)
    const float pi_rc = 3.14159265358979f / myrc;

    // ======================= Stage 1: rsf chunks =======================
    for (int chunk = blockIdx.x; chunk < NCHUNK; chunk += GRID) {
        const int baseAtom = chunk * APB;       // atom = b*N + n

        // ---------------- Phase A: one warp per atom ----------------
        if (warp < APB) {
            const int atom = baseAtom + warp;
            const int b    = atom >> 11;
            const float* xp = X + atom * 3;
            const float x0 = xp[0], x1 = xp[1], x2 = xp[2];

            const int nb = Nbrs [atom * MM + lane];
            const int z  = NbrsZ[atom * MM + lane];
            const float* np_ = X + ((b << 11) + nb) * 3;
            const float dx = np_[0] - x0;
            const float dy = np_[1] - x1;
            const float dz = np_[2] - x2;
            const float R  = sqrt_fast(dx*dx + dy*dy + dz*dz);

            int t = -1;
            if      (z == 1)  t = 0;
            else if (z == 6)  t = 1;
            else if (z == 7)  t = 2;
            else if (z == 8)  t = 3;
            else if (z == 16) t = 4;

            const unsigned mask = __ballot_sync(0xffffffffu, t >= 0);
            if (t >= 0) {
                const int pos = __popc(mask & ((1u << lane) - 1u));
                sRT[warp][pos] = make_float2(R, __int_as_float(t));
            }
            if (lane == 0) sCnt[warp] = __popc(mask);
        }
        __syncthreads();

        // ---------------- Phase B: 384 threads, thread=(g,j) ----------------
        const int atom = baseAtom + g;
        const float2* rt = sRT[g];
        const int total  = sCnt[g];

        float acc[TT];
        #pragma unroll
        for (int tt = 0; tt < TT; tt++) acc[tt] = 0.0f;

        int m = 0;
        for (; m + 2 <= total; m += 2) {
            const float2 a0 = rt[m];
            const float2 a1 = rt[m + 1];
            const float R0 = a0.x, R1 = a1.x;
            const int   t0 = __float_as_int(a0.y);
            const int   t1 = __float_as_int(a1.y);
            const float d0 = R0 - myrs;
            const float d1 = R1 - myrs;
            const float e0 = ex2_fast(nre2 * d0 * d0);
            const float e1 = ex2_fast(nre2 * d1 * d1);
            const float c0 = __cosf(R0 * pi_rc);
            const float c1 = __cosf(R1 * pi_rc);
            float f0 = fmaf(c0, 0.5f, 0.5f);
            float f1 = fmaf(c1, 0.5f, 0.5f);
            f0 = (R0 <= myrc) ? f0 : 0.0f;
            f1 = (R1 <= myrc) ? f1 : 0.0f;
            const float v0 = e0 * f0;
            const float v1 = e1 * f1;
            #pragma unroll
            for (int tt = 0; tt < TT; tt++) {
                if (t0 == tt) acc[tt] += v0;
                if (t1 == tt) acc[tt] += v1;
            }
        }
        if (m < total) {
            const float2 a0 = rt[m];
            const float R0 = a0.x;
            const int   t0 = __float_as_int(a0.y);
            const float d0 = R0 - myrs;
            const float e0 = ex2_fast(nre2 * d0 * d0);
            const float c0 = __cosf(R0 * pi_rc);
            float f0 = fmaf(c0, 0.5f, 0.5f);
            f0 = (R0 <= myrc) ? f0 : 0.0f;
            const float v0 = e0 * f0;
            #pragma unroll
            for (int tt = 0; tt < TT; tt++) {
                if (t0 == tt) acc[tt] += v0;
            }
        }

        float s = 0.0f, s2 = 0.0f;
        {
            float* op = out + (size_t)atom * CC;
            #pragma unroll
            for (int tt = 0; tt < TT; tt++) {
                const float a = acc[tt];
                op[tt * PP + j] = a;
                s  += a;
                s2 = fmaf(a, a, s2);
            }
        }
        sPart[tid] = make_float2(s, s2);
        __syncthreads();

        // ---------------- Phase C: per-atom reduce -> g_part ----------------
        if (warp < APB) {
            const float2 p0 = sPart[warp * PP + lane];
            float rs_ = p0.x;
            float r2_ = p0.y;
            if (lane < PP - 32) {
                const float2 p1 = sPart[warp * PP + 32 + lane];
                rs_ += p1.x;
                r2_ += p1.y;
            }
            #pragma unroll
            for (int o = 16; o > 0; o >>= 1) {
                rs_ += __shfl_down_sync(0xffffffffu, rs_, o);
                r2_ += __shfl_down_sync(0xffffffffu, r2_, o);
            }
            if (lane == 0) g_part[baseAtom + warp] = make_float2(rs_, r2_);
        }
        __syncthreads();
    }

    // ======================= Grid barrier =======================
    // Monotonic counter: target = next multiple of GRID above my ticket.
    __threadfence();               // make out/g_part writes visible
    __shared__ unsigned sTarget;
    __syncthreads();
    if (tid == 0) {
        const unsigned old = atomicAdd(&g_bar, 1u);
        sTarget = (old / GRID + 1u) * GRID;
    }
    __syncthreads();
    if (tid == 0) {
        volatile unsigned* p = &g_bar;
        while (*p < sTarget) { }
    }
    __syncthreads();
    __threadfence();

    // ======================= Stage 2: BatchNorm =======================
    float4* out4 = (float4*)out;
    for (int n = blockIdx.x; n < NN; n += GRID) {
        // stats: warp 0 reduces the 16 per-atom partials
        if (tid < 32) {
            float s = 0.0f, s2 = 0.0f;
            if (tid < BB) {
                const float2 p = g_part[tid * NN + n];
                s = p.x; s2 = p.y;
            }
            #pragma unroll
            for (int o = 8; o > 0; o >>= 1) {
                s  += __shfl_down_sync(0xffffffffu, s,  o);
                s2 += __shfl_down_sync(0xffffffffu, s2, o);
            }
            if (tid == 0) {
                const float invn = 1.0f / (float)(BB * CC);
                const float mean = s * invn;
                float var = s2 * invn - mean * mean;
                var = fmaxf(var, 0.0f);
                sMean = mean;
                sInv  = rsqrtf(var + 1e-5f);
            }
        }
        __syncthreads();

        const float mean = sMean;
        const float inv  = sInv;

        // 960 float4 per n over 384 threads: i, i+384, i+768 (last partial).
        #pragma unroll
        for (int base = 0; base < 960; base += TH1) {
            const int i = base + tid;
            if (i < 960) {
                const int b  = i / 60;
                const int c4 = i % 60;
                const size_t idx = (size_t)(b * NN + n) * (CC / 4) + c4;
                float4 v = out4[idx];
                v.x = (v.x - mean) * inv;
                v.y = (v.y - mean) * inv;
                v.z = (v.z - mean) * inv;
                v.w = (v.w - mean) * inv;
                out4[idx] = v;
            }
        }
        __syncthreads();
    }
}

// ---------------------------------------------------------------------------
extern "C" void kernel_launch(void* const* d_in, const int* in_sizes, int n_in,
                              void* d_out, int out_size)
{
    const float* X     = (const float*)d_in[0];
    const float* rc    = (const float*)d_in[1];
    const float* rs    = (const float*)d_in[2];
    const float* re    = (const float*)d_in[3];
    const int*   Nbrs  = (const int*)  d_in[4];
    const int*   NbrsZ = (const int*)  d_in[5];

    fused_kernel<<<GRID, TH1>>>(X, rc, rs, re, Nbrs, NbrsZ, (float*)d_out);
}

// round 13
// speedup vs baseline: 1.1978x; 1.1978x over previous
#include <cuda_runtime.h>
#include <math.h>

#define BB 16
#define NN 2048
#define MM 32
#define PP 48
#define TT 5
#define CC (PP*TT)   // 240

#define APB 8            // atoms per block
#define TH1 (APB*PP)     // 384 threads = 12 warps; phase A uses warps 0..7

// Per-atom BN partials: g_part[atom] = {sum, sumsq} over 240 channels.
// Unconditionally overwritten every launch -> deterministic, no zeroing.
__device__ float2 g_part[BB * NN];

__device__ __forceinline__ float ex2_fast(float x) {
    float r; asm("ex2.approx.f32 %0, %1;" : "=f"(r) : "f"(x)); return r;
}
__device__ __forceinline__ float sqrt_fast(float x) {
    float r; asm("sqrt.approx.f32 %0, %1;" : "=f"(r) : "f"(x)); return r;
}

// ---------------------------------------------------------------------------
// Kernel 1: radial symmetry functions + BN partials.
// R6 structure; phase B inner loop is single-wide (low reg pressure) and the
// block is capped at 42 regs via __launch_bounds__(384,4) -> 4 blocks/SM
// (75% occupancy vs 56% before). Profile showed issue-bound at low occ.
// ---------------------------------------------------------------------------
__global__ __launch_bounds__(TH1, 4)
void rsf_kernel(const float* __restrict__ X,
                const float* __restrict__ rc,
                const float* __restrict__ rs,
                const float* __restrict__ re,
                const int*   __restrict__ Nbrs,
                const int*   __restrict__ NbrsZ,
                float*       __restrict__ out)
{
    __shared__ float2 sRT[APB][MM];
    __shared__ int    sCnt[APB];
    __shared__ float2 sPart[TH1];

    const int tid  = threadIdx.x;
    const int warp = tid >> 5;
    const int lane = tid & 31;
    const int baseAtom = blockIdx.x * APB;      // atom = b*N + n

    // ---------------- Phase A: one warp per atom ----------------
    if (warp < APB) {
        const int atom = baseAtom + warp;
        const int b    = atom >> 11;
        const float* xp = X + atom * 3;
        const float x0 = xp[0], x1 = xp[1], x2 = xp[2];

        const int nb = Nbrs [atom * MM + lane];
        const int z  = NbrsZ[atom * MM + lane];
        const float* np_ = X + ((b << 11) + nb) * 3;
        const float dx = np_[0] - x0;
        const float dy = np_[1] - x1;
        const float dz = np_[2] - x2;
        const float R  = sqrt_fast(dx*dx + dy*dy + dz*dz);

        int t = -1;
        if      (z == 1)  t = 0;
        else if (z == 6)  t = 1;
        else if (z == 7)  t = 2;
        else if (z == 8)  t = 3;
        else if (z == 16) t = 4;

        const unsigned mask = __ballot_sync(0xffffffffu, t >= 0);
        if (t >= 0) {
            const int pos = __popc(mask & ((1u << lane) - 1u));
            sRT[warp][pos] = make_float2(R, __int_as_float(t));
        }
        if (lane == 0) sCnt[warp] = __popc(mask);
    }
    __syncthreads();

    // ---------------- Phase B: 384 threads, thread=(g,j) ----------------
    const int g = tid / PP;        // atom within block
    const int j = tid % PP;        // radial index p
    const int atom = baseAtom + g;

    const float myrc  = rc[j];
    const float myrs  = rs[j];
    const float nre2  = -re[j] * 1.44269504088896f;  // fold log2(e)
    const float pi_rc = 3.14159265358979f / myrc;
    const float2* rt  = sRT[g];
    const int total   = sCnt[g];

    float acc[TT];
    #pragma unroll
    for (int tt = 0; tt < TT; tt++) acc[tt] = 0.0f;

    for (int m = 0; m < total; m++) {
        const float2 a0 = rt[m];
        const float R0 = a0.x;
        const int   t0 = __float_as_int(a0.y);
        const float d0 = R0 - myrs;
        const float e0 = ex2_fast(nre2 * d0 * d0);
        const float c0 = __cosf(R0 * pi_rc);
        float f0 = fmaf(c0, 0.5f, 0.5f);
        f0 = (R0 <= myrc) ? f0 : 0.0f;
        const float v0 = e0 * f0;
        #pragma unroll
        for (int tt = 0; tt < TT; tt++) {
            if (t0 == tt) acc[tt] += v0;
        }
    }

    float s = 0.0f, s2 = 0.0f;
    {
        float* op = out + (size_t)atom * CC;
        #pragma unroll
        for (int tt = 0; tt < TT; tt++) {
            const float a = acc[tt];
            op[tt * PP + j] = a;
            s  += a;
            s2 = fmaf(a, a, s2);
        }
    }
    sPart[tid] = make_float2(s, s2);
    __syncthreads();

    // ---------------- Phase C: per-atom reduce of (s,s2) ----------------
    if (warp < APB) {
        const float2 p0 = sPart[warp * PP + lane];
        float s  = p0.x;
        float s2 = p0.y;
        if (lane < PP - 32) {
            const float2 p1 = sPart[warp * PP + 32 + lane];
            s  += p1.x;
            s2 += p1.y;
        }
        #pragma unroll
        for (int o = 16; o > 0; o >>= 1) {
            s  += __shfl_down_sync(0xffffffffu, s,  o);
            s2 += __shfl_down_sync(0xffffffffu, s2, o);
        }
        if (lane == 0) g_part[baseAtom + warp] = make_float2(s, s2);
    }
}

// ---------------------------------------------------------------------------
// Kernel 2: BatchNorm normalize (R7 float4 version, verbatim — best measured
// norm at ~12.1us). One block per n; warp 0 reduces 16 per-atom partials ->
// mean/inv; tid<240 handles float4 column c4=tid%60 for rows b=(tid/60)*4+r.
// ---------------------------------------------------------------------------
__global__ __launch_bounds__(256)
void norm_kernel(float4* __restrict__ out4)
{
    const int n   = blockIdx.x;
    const int tid = threadIdx.x;

    __shared__ float sMean, sInv;

    if (tid < 32) {
        float s = 0.0f, s2 = 0.0f;
        if (tid < BB) {
            const float2 p = g_part[tid * NN + n];
            s = p.x; s2 = p.y;
        }
        #pragma unroll
        for (int o = 8; o > 0; o >>= 1) {
            s  += __shfl_down_sync(0xffffffffu, s,  o);
            s2 += __shfl_down_sync(0xffffffffu, s2, o);
        }
        if (tid == 0) {
            const float invn = 1.0f / (float)(BB * CC);
            const float mean = s * invn;
            float var = s2 * invn - mean * mean;
            var = fmaxf(var, 0.0f);
            sMean = mean;
            sInv  = rsqrtf(var + 1e-5f);
        }
    }
    __syncthreads();

    if (tid < 240) {
        const float mean = sMean;
        const float inv  = sInv;
        const int bq = tid / 60;              // 0..3
        const int c4 = tid % 60;              // float4 index within row

        float4 v[4];
        size_t idx[4];
        #pragma unroll
        for (int r = 0; r < 4; r++) {
            const int b = bq * 4 + r;
            idx[r] = (size_t)(b * NN + n) * (CC / 4) + c4;
            v[r] = out4[idx[r]];
        }
        #pragma unroll
        for (int r = 0; r < 4; r++) {
            v[r].x = (v[r].x - mean) * inv;
            v[r].y = (v[r].y - mean) * inv;
            v[r].z = (v[r].z - mean) * inv;
            v[r].w = (v[r].w - mean) * inv;
            out4[idx[r]] = v[r];
        }
    }
}

// ---------------------------------------------------------------------------
extern "C" void kernel_launch(void* const* d_in, const int* in_sizes, int n_in,
                              void* d_out, int out_size)
{
    const float* X     = (const float*)d_in[0];
    const float* rc    = (const float*)d_in[1];
    const float* rs    = (const float*)d_in[2];
    const float* re    = (const float*)d_in[3];
    const int*   Nbrs  = (const int*)  d_in[4];
    const int*   NbrsZ = (const int*)  d_in[5];

    const int nAtoms = BB * NN;                 // 32768
    rsf_kernel<<<nAtoms / APB, TH1>>>(X, rc, rs, re, Nbrs, NbrsZ, (float*)d_out);
    norm_kernel<<<NN, 256>>>((float4*)d_out);
}

// round 14
// speedup vs baseline: 1.3944x; 1.1641x over previous
#include <cuda_runtime.h>
#include <math.h>

#define BB 16
#define NN 2048
#define MM 32
#define PP 48
#define TT 5
#define CC (PP*TT)   // 240

#define APB 8            // atoms per block
#define TH1 (APB*PP)     // 384 threads = 12 warps; phase A uses warps 0..7
#define NPB 4            // n-columns per norm block

// Per-atom BN partials: g_part[atom] = {sum, sumsq} over 240 channels.
// Unconditionally overwritten every launch -> deterministic, no zeroing.
__device__ float2 g_part[BB * NN];

__device__ __forceinline__ float ex2_fast(float x) {
    float r; asm("ex2.approx.f32 %0, %1;" : "=f"(r) : "f"(x)); return r;
}
__device__ __forceinline__ float sqrt_fast(float x) {
    float r; asm("sqrt.approx.f32 %0, %1;" : "=f"(r) : "f"(x)); return r;
}

// ---------------------------------------------------------------------------
// Kernel 1: radial symmetry functions + BN partials (R6/R10 code verbatim —
// best measured rsf; natural register allocation, no launch_bounds cap).
// ---------------------------------------------------------------------------
__global__ __launch_bounds__(TH1)
void rsf_kernel(const float* __restrict__ X,
                const float* __restrict__ rc,
                const float* __restrict__ rs,
                const float* __restrict__ re,
                const int*   __restrict__ Nbrs,
                const int*   __restrict__ NbrsZ,
                float*       __restrict__ out)
{
    __shared__ float2 sRT[APB][MM];
    __shared__ int    sCnt[APB];
    __shared__ float2 sPart[TH1];

    const int tid  = threadIdx.x;
    const int warp = tid >> 5;
    const int lane = tid & 31;
    const int baseAtom = blockIdx.x * APB;      // atom = b*N + n

    // ---------------- Phase A: one warp per atom ----------------
    if (warp < APB) {
        const int atom = baseAtom + warp;
        const int b    = atom >> 11;
        const float* xp = X + atom * 3;
        const float x0 = xp[0], x1 = xp[1], x2 = xp[2];

        const int nb = Nbrs [atom * MM + lane];
        const int z  = NbrsZ[atom * MM + lane];
        const float* np_ = X + ((b << 11) + nb) * 3;
        const float dx = np_[0] - x0;
        const float dy = np_[1] - x1;
        const float dz = np_[2] - x2;
        const float R  = sqrt_fast(dx*dx + dy*dy + dz*dz);

        int t = -1;
        if      (z == 1)  t = 0;
        else if (z == 6)  t = 1;
        else if (z == 7)  t = 2;
        else if (z == 8)  t = 3;
        else if (z == 16) t = 4;

        const unsigned mask = __ballot_sync(0xffffffffu, t >= 0);
        if (t >= 0) {
            const int pos = __popc(mask & ((1u << lane) - 1u));
            sRT[warp][pos] = make_float2(R, __int_as_float(t));
        }
        if (lane == 0) sCnt[warp] = __popc(mask);
    }
    __syncthreads();

    // ---------------- Phase B: 384 threads, thread=(g,j) ----------------
    const int g = tid / PP;        // atom within block
    const int j = tid % PP;        // radial index p
    const int atom = baseAtom + g;

    const float myrc  = rc[j];
    const float myrs  = rs[j];
    const float nre2  = -re[j] * 1.44269504088896f;  // fold log2(e)
    const float pi_rc = 3.14159265358979f / myrc;
    const float2* rt  = sRT[g];
    const int total   = sCnt[g];

    float acc[TT];
    #pragma unroll
    for (int tt = 0; tt < TT; tt++) acc[tt] = 0.0f;

    int m = 0;
    for (; m + 2 <= total; m += 2) {
        const float2 a0 = rt[m];
        const float2 a1 = rt[m + 1];
        const float R0 = a0.x, R1 = a1.x;
        const int   t0 = __float_as_int(a0.y);
        const int   t1 = __float_as_int(a1.y);
        const float d0 = R0 - myrs;
        const float d1 = R1 - myrs;
        const float e0 = ex2_fast(nre2 * d0 * d0);
        const float e1 = ex2_fast(nre2 * d1 * d1);
        const float c0 = __cosf(R0 * pi_rc);
        const float c1 = __cosf(R1 * pi_rc);
        float f0 = fmaf(c0, 0.5f, 0.5f);
        float f1 = fmaf(c1, 0.5f, 0.5f);
        f0 = (R0 <= myrc) ? f0 : 0.0f;
        f1 = (R1 <= myrc) ? f1 : 0.0f;
        const float v0 = e0 * f0;
        const float v1 = e1 * f1;
        #pragma unroll
        for (int tt = 0; tt < TT; tt++) {
            if (t0 == tt) acc[tt] += v0;
            if (t1 == tt) acc[tt] += v1;
        }
    }
    if (m < total) {
        const float2 a0 = rt[m];
        const float R0 = a0.x;
        const int   t0 = __float_as_int(a0.y);
        const float d0 = R0 - myrs;
        const float e0 = ex2_fast(nre2 * d0 * d0);
        const float c0 = __cosf(R0 * pi_rc);
        float f0 = fmaf(c0, 0.5f, 0.5f);
        f0 = (R0 <= myrc) ? f0 : 0.0f;
        const float v0 = e0 * f0;
        #pragma unroll
        for (int tt = 0; tt < TT; tt++) {
            if (t0 == tt) acc[tt] += v0;
        }
    }

    float s = 0.0f, s2 = 0.0f;
    {
        float* op = out + (size_t)atom * CC;
        #pragma unroll
        for (int tt = 0; tt < TT; tt++) {
            const float a = acc[tt];
            op[tt * PP + j] = a;
            s  += a;
            s2 = fmaf(a, a, s2);
        }
    }
    sPart[tid] = make_float2(s, s2);
    __syncthreads();

    // ---------------- Phase C: per-atom reduce of (s,s2) ----------------
    if (warp < APB) {
        const float2 p0 = sPart[warp * PP + lane];
        float s  = p0.x;
        float s2 = p0.y;
        if (lane < PP - 32) {
            const float2 p1 = sPart[warp * PP + 32 + lane];
            s  += p1.x;
            s2 += p1.y;
        }
        #pragma unroll
        for (int o = 16; o > 0; o >>= 1) {
            s  += __shfl_down_sync(0xffffffffu, s,  o);
            s2 += __shfl_down_sync(0xffffffffu, s2, o);
        }
        if (lane == 0) g_part[baseAtom + warp] = make_float2(s, s2);
    }
}

// ---------------------------------------------------------------------------
// Kernel 2: BatchNorm normalize, restructured. 512 blocks x 256 threads;
// block handles NPB=4 n-columns. Stats: warps 0..3 IN PARALLEL each reduce
// the 16 per-atom partials of one n (lane<16 loads, full-warp shfl reduce).
// Stream: all 256 threads normalize 4 x 960 float4 (15 vec ops/thread).
// ---------------------------------------------------------------------------
__global__ __launch_bounds__(256)
void norm_kernel(float4* __restrict__ out4)
{
    const int n0  = blockIdx.x * NPB;
    const int tid = threadIdx.x;
    const int warp = tid >> 5;
    const int lane = tid & 31;

    __shared__ float2 sStat[NPB];    // {mean, inv} per n

    if (warp < NPB) {
        const int n = n0 + warp;
        float s = 0.0f, s2 = 0.0f;
        if (lane < BB) {
            const float2 p = g_part[lane * NN + n];
            s = p.x; s2 = p.y;
        }
        #pragma unroll
        for (int o = 16; o > 0; o >>= 1) {
            s  += __shfl_down_sync(0xffffffffu, s,  o);
            s2 += __shfl_down_sync(0xffffffffu, s2, o);
        }
        if (lane == 0) {
            const float invn = 1.0f / (float)(BB * CC);
            const float mean = s * invn;
            float var = s2 * invn - mean * mean;
            var = fmaxf(var, 0.0f);
            sStat[warp] = make_float2(mean, rsqrtf(var + 1e-5f));
        }
    }
    __syncthreads();

    #pragma unroll
    for (int nl = 0; nl < NPB; nl++) {
        const int n = n0 + nl;
        const float mean = sStat[nl].x;
        const float inv  = sStat[nl].y;

        // 960 float4 per n over 256 threads: items tid, tid+256, tid+512,
        // tid+768 (last predicated: only tid < 192).
        float4 v[4];
        size_t idx[4];
        #pragma unroll
        for (int r = 0; r < 4; r++) {
            const int i = r * 256 + tid;
            if (i < 960) {
                const int b  = i / 60;
                const int c4 = i % 60;
                idx[r] = (size_t)(b * NN + n) * (CC / 4) + c4;
                v[r] = out4[idx[r]];
            }
        }
        #pragma unroll
        for (int r = 0; r < 4; r++) {
            const int i = r * 256 + tid;
            if (i < 960) {
                v[r].x = (v[r].x - mean) * inv;
                v[r].y = (v[r].y - mean) * inv;
                v[r].z = (v[r].z - mean) * inv;
                v[r].w = (v[r].w - mean) * inv;
                out4[idx[r]] = v[r];
            }
        }
    }
}

// ---------------------------------------------------------------------------
extern "C" void kernel_launch(void* const* d_in, const int* in_sizes, int n_in,
                              void* d_out, int out_size)
{
    const float* X     = (const float*)d_in[0];
    const float* rc    = (const float*)d_in[1];
    const float* rs    = (const float*)d_in[2];
    const float* re    = (const float*)d_in[3];
    const int*   Nbrs  = (const int*)  d_in[4];
    const int*   NbrsZ = (const int*)  d_in[5];

    const int nAtoms = BB * NN;                 // 32768
    rsf_kernel<<<nAtoms / APB, TH1>>>(X, rc, rs, re, Nbrs, NbrsZ, (float*)d_out);
    norm_kernel<<<NN / NPB, 256>>>((float4*)d_out);
}